// round 5
// baseline (speedup 1.0000x reference)
#include <cuda_runtime.h>
#include <cstdint>

#define NSAMP 256
#define EMB   120
#define DIN   64
#define MODES 16
#define NPH   8

#define PIf 3.14159265358979323846f

// Persistent scratch for V, stored TRANSPOSED: [n][c][m] (c=0..7, m=0..15)
// 256 * 8 * 16 float2 = 256 KB
__device__ float2 g_V[NSAMP * NPH * MODES];

__device__ __forceinline__ float2 cmul(float2 a, float2 b) {
    return make_float2(a.x * b.x - a.y * b.y, a.x * b.y + a.y * b.x);
}

// Packed dual-FMA: d = a * b + c elementwise on float2 lanes (one FFMA2 issue slot)
__device__ __forceinline__ float2 ffma2(float2 a, float2 b, float2 c) {
    float2 d;
    asm("{\n\t"
        ".reg .b64 ra, rb, rc, rd;\n\t"
        "mov.b64 ra, {%2, %3};\n\t"
        "mov.b64 rb, {%4, %5};\n\t"
        "mov.b64 rc, {%6, %7};\n\t"
        "fma.rn.f32x2 rd, ra, rb, rc;\n\t"
        "mov.b64 {%0, %1}, rd;\n\t"
        "}"
        : "=f"(d.x), "=f"(d.y)
        : "f"(a.x), "f"(a.y), "f"(b.x), "f"(b.y), "f"(c.x), "f"(c.y));
    return d;
}

// ---------------------------------------------------------------------------
// Kernel A: x_emb = sigmoid(x @ W^T + b); build V[n] (16x8 complex) per sample
// One block per sample, 128 threads. Stores V transposed [c][m].
// ---------------------------------------------------------------------------
__global__ void __launch_bounds__(128) emb_v_kernel(
    const float* __restrict__ x,
    const float* __restrict__ W,
    const float* __restrict__ b,
    float* __restrict__ out_emb)
{
    const int n = blockIdx.x;
    const int t = threadIdx.x;

    __shared__ float xs[DIN];
    __shared__ float semb[EMB];
    __shared__ float4 trig[60];   // (ct, st, cp, sp) per 2x2 block

    if (t < DIN) xs[t] = x[n * DIN + t];
    __syncthreads();

    if (t < EMB) {
        float acc = b[t];
        const float* wr = W + t * DIN;
        #pragma unroll
        for (int j = 0; j < DIN; j++) acc += xs[j] * wr[j];
        float s = 1.0f / (1.0f + expf(-acc));
        semb[t] = s;
        out_emb[n * EMB + t] = s;
    }
    __syncthreads();

    if (t < 60) {
        float th = semb[2 * t]     * (0.5f * PIf);
        float ph = semb[2 * t + 1] * (2.0f * PIf);
        float st_, ct_, sp_, cp_;
        sincosf(th, &st_, &ct_);
        sincosf(ph, &sp_, &cp_);
        trig[t] = make_float4(ct_, st_, cp_, sp_);
    }
    __syncthreads();

    // Threads 0..7: propagate column c of I[:, :8] through 8 brick layers.
    if (t < NPH) {
        float2 v[MODES];
        #pragma unroll
        for (int m = 0; m < MODES; m++)
            v[m] = make_float2((m == t) ? 1.0f : 0.0f, 0.0f);

        int nbefore = 0;
        #pragma unroll
        for (int d = 0; d < 8; d++) {
            const int nb  = (d & 1) ? 7 : 8;
            const int off = (d & 1);
            #pragma unroll
            for (int k = 0; k < 8; k++) {
                if (k < nb) {
                    float4 tg = trig[nbefore + k];   // ct, st, cp, sp
                    const int r0 = off + 2 * k;
                    float2 t0 = v[r0], t1 = v[r0 + 1];
                    float2 epct = make_float2(tg.z * tg.x, tg.w * tg.x);
                    float2 epst = make_float2(tg.z * tg.y, tg.w * tg.y);
                    float2 n0 = cmul(epct, t0);
                    n0.x -= tg.y * t1.x;  n0.y -= tg.y * t1.y;
                    float2 n1 = cmul(epst, t0);
                    n1.x += tg.x * t1.x;  n1.y += tg.x * t1.y;
                    v[r0] = n0;  v[r0 + 1] = n1;
                }
            }
            nbefore += nb;
        }
        // transposed store: [n][c=t][m], contiguous per thread
        #pragma unroll
        for (int m = 0; m < MODES; m++)
            g_V[n * (NPH * MODES) + t * MODES + m] = v[m];
    }
}

// ---------------------------------------------------------------------------
// Kernel B (triangular): compute only macro-tiles (qa, bg) with bg >= qa.
// One warp per pair (a, b); writes K[a,b] and K[b,a]. Diagonal = 1.0.
// G phase uses transposed [col][mode] layout with pad-18 rows -> conflict-free
// LDS.128. Ryser row-sum updates use packed fma.rn.f32x2.
// ---------------------------------------------------------------------------
#define VROW 18   // padded row stride (float2 units): 144B -> 4-bank step per row

__global__ void __launch_bounds__(256, 4) pair_kernel_tri(float* __restrict__ Kout)
{
    const int tid  = threadIdx.x;
    const int w    = tid >> 5;          // warp 0..7
    const int lane = tid & 31;

    // Decode macro-tile: t in [0,528) -> (bg, qa) with qa <= bg
    const int tIdx = blockIdx.x >> 3;
    const int ai   = blockIdx.x & 7;
    int bg = (int)((sqrtf(8.0f * (float)tIdx + 1.0f) - 1.0f) * 0.5f);
    if ((bg + 1) * (bg + 2) / 2 <= tIdx) bg++;
    if (bg * (bg + 1) / 2 > tIdx) bg--;
    const int qa   = tIdx - bg * (bg + 1) / 2;
    const int a    = qa * 8 + ai;       // 0..255
    const int bcol = bg * 8 + w;        // 0..255

    __shared__ alignas(16) float2 sVa[NPH * VROW];          // [i*18 + m]
    __shared__ alignas(16) float2 sVb[8][NPH * VROW];       // [w][j*18 + m]
    __shared__ float2 sA[8][64];                            // [i*8 + j]

    // Load V[a] (block-wide, transposed+padded) and V[b] (per warp)
    if (tid < NPH * MODES) {
        const int row = tid >> 4, m = tid & 15;
        sVa[row * VROW + m] = g_V[a * (NPH * MODES) + tid];
    }
    #pragma unroll
    for (int r = 0; r < 4; r++) {
        const int idx = lane + r * 32;
        const int row = idx >> 4, m = idx & 15;
        sVb[w][row * VROW + m] = g_V[bcol * (NPH * MODES) + idx];
    }
    __syncthreads();

    if (bcol < a) return;                       // mirror handles it
    if (bcol == a) {                            // diagonal forced to 1.0
        if (lane == 0) Kout[a * NSAMP + a] = 1.0f;
        return;
    }

    // G[i][j] = sum_m conj(Va[m][i]) * Vb[m][j]; lane computes 2 entries.
    // float4 loads: 2 modes per LDS.128, conflict-free thanks to pad 18.
    #pragma unroll
    for (int e = 0; e < 2; e++) {
        const int idx = lane + e * 32;
        const int i = idx >> 3, j = idx & 7;
        const float4* pa = (const float4*)&sVa[i * VROW];
        const float4* pb = (const float4*)&sVb[w][j * VROW];
        float2 acc = make_float2(0.0f, 0.0f);
        #pragma unroll
        for (int mm = 0; mm < 8; mm++) {
            float4 va2 = pa[mm];   // modes 2mm, 2mm+1 of column i
            float4 vb2 = pb[mm];
            acc.x += va2.x * vb2.x + va2.y * vb2.y;
            acc.y += va2.x * vb2.y - va2.y * vb2.x;
            acc.x += va2.z * vb2.z + va2.w * vb2.w;
            acc.y += va2.z * vb2.w - va2.w * vb2.z;
        }
        sA[w][i * 8 + j] = acc;
    }
    __syncwarp();

    // Cache columns 0..1 in registers (bits 0/1 flip 6 of 7 inner Gray steps).
    float2 cr[2][8];
    #pragma unroll
    for (int j = 0; j < 2; j++)
        #pragma unroll
        for (int i = 0; i < 8; i++)
            cr[j][i] = sA[w][i * 8 + j];

    // Initial subset: gray(8*lane) = (lane<<3) ^ (lane<<2), bits >= 2 only.
    unsigned g = (((unsigned)lane << 3) ^ ((unsigned)lane << 2)) & 0xFFu;

    float2 rs[8];
    #pragma unroll
    for (int i = 0; i < 8; i++) rs[i] = make_float2(0.0f, 0.0f);

    #pragma unroll
    for (int jb = 2; jb < 8; jb++) {
        const float msk = (float)((g >> jb) & 1u);
        const float2 mp = make_float2(msk, msk);
        #pragma unroll
        for (int i = 0; i < 8; i++)
            rs[i] = ffma2(mp, sA[w][i * 8 + jb], rs[i]);
    }

    float2 acc = make_float2(0.0f, 0.0f);
    const int CTZ[8] = {0, 0, 1, 0, 2, 0, 1, 0};

    #pragma unroll
    for (int k = 0; k < 8; k++) {
        if (k > 0) {
            const int jb = CTZ[k];
            g ^= (1u << jb);
            const float s = ((g >> jb) & 1u) ? 1.0f : -1.0f;
            const float2 sp = make_float2(s, s);
            if (jb < 2) {
                #pragma unroll
                for (int i = 0; i < 8; i++)
                    rs[i] = ffma2(sp, cr[jb][i], rs[i]);
            } else {
                #pragma unroll
                for (int i = 0; i < 8; i++)
                    rs[i] = ffma2(sp, sA[w][i * 8 + 2], rs[i]);
            }
        }
        // product of 8 complex row sums (tree for ILP)
        float2 p01 = cmul(rs[0], rs[1]);
        float2 p23 = cmul(rs[2], rs[3]);
        float2 p45 = cmul(rs[4], rs[5]);
        float2 p67 = cmul(rs[6], rs[7]);
        float2 p = cmul(cmul(p01, p23), cmul(p45, p67));
        // sign parity(gray(8*lane+k)) == k&1
        if (k & 1) { acc.x -= p.x; acc.y -= p.y; }
        else       { acc.x += p.x; acc.y += p.y; }
    }

    // Warp reduce (complex)
    #pragma unroll
    for (int off = 16; off > 0; off >>= 1) {
        acc.x += __shfl_xor_sync(0xFFFFFFFFu, acc.x, off);
        acc.y += __shfl_xor_sync(0xFFFFFFFFu, acc.y, off);
    }

    if (lane == 0) {
        float kv = acc.x * acc.x + acc.y * acc.y;
        Kout[a * NSAMP + bcol] = kv;
        Kout[bcol * NSAMP + a] = kv;
    }
}

// ---------------------------------------------------------------------------
extern "C" void kernel_launch(void* const* d_in, const int* in_sizes, int n_in,
                              void* d_out, int out_size)
{
    const float* x = (const float*)d_in[0];   // (256, 64)
    const float* W = (const float*)d_in[1];   // (120, 64)
    const float* b = (const float*)d_in[2];   // (120,)
    float* out = (float*)d_out;               // [x_emb (30720) | K (65536)]

    emb_v_kernel<<<NSAMP, 128>>>(x, W, b, out);
    pair_kernel_tri<<<528 * 8, 256>>>(out + NSAMP * EMB);
}

// round 6
// speedup vs baseline: 1.0896x; 1.0896x over previous
#include <cuda_runtime.h>
#include <cstdint>

#define NSAMP 256
#define EMB   120
#define DIN   64
#define MODES 16
#define NPH   8

#define PIf 3.14159265358979323846f

typedef unsigned long long ull;

// Persistent scratch for V, stored TRANSPOSED: [n][c][m] (c=0..7, m=0..15)
__device__ float2 g_V[NSAMP * NPH * MODES];

__device__ __forceinline__ float2 cmul(float2 a, float2 b) {
    return make_float2(a.x * b.x - a.y * b.y, a.x * b.y + a.y * b.x);
}

// Packed dual-FMA on native 64-bit operands: no pack/unpack movs at the call.
__device__ __forceinline__ ull ffma2p(ull a, ull b, ull c) {
    ull d;
    asm("fma.rn.f32x2 %0, %1, %2, %3;" : "=l"(d) : "l"(a), "l"(b), "l"(c));
    return d;
}
__device__ __forceinline__ ull pack2(float x, float y) {
    ull d; asm("mov.b64 %0, {%1, %2};" : "=l"(d) : "f"(x), "f"(y)); return d;
}
__device__ __forceinline__ float2 unpack2(ull a) {
    float2 f; asm("mov.b64 {%0, %1}, %2;" : "=f"(f.x), "=f"(f.y) : "l"(a)); return f;
}

// ---------------------------------------------------------------------------
// Kernel A: x_emb = sigmoid(x @ W^T + b); build V[n] (16x8 complex) per sample
// ---------------------------------------------------------------------------
__global__ void __launch_bounds__(128) emb_v_kernel(
    const float* __restrict__ x,
    const float* __restrict__ W,
    const float* __restrict__ b,
    float* __restrict__ out_emb)
{
    const int n = blockIdx.x;
    const int t = threadIdx.x;

    __shared__ float xs[DIN];
    __shared__ float semb[EMB];
    __shared__ float4 trig[60];   // (ct, st, cp, sp) per 2x2 block

    if (t < DIN) xs[t] = x[n * DIN + t];
    __syncthreads();

    if (t < EMB) {
        float acc = b[t];
        const float* wr = W + t * DIN;
        #pragma unroll
        for (int j = 0; j < DIN; j++) acc += xs[j] * wr[j];
        float s = 1.0f / (1.0f + expf(-acc));
        semb[t] = s;
        out_emb[n * EMB + t] = s;
    }
    __syncthreads();

    if (t < 60) {
        float th = semb[2 * t]     * (0.5f * PIf);
        float ph = semb[2 * t + 1] * (2.0f * PIf);
        float st_, ct_, sp_, cp_;
        sincosf(th, &st_, &ct_);
        sincosf(ph, &sp_, &cp_);
        trig[t] = make_float4(ct_, st_, cp_, sp_);
    }
    __syncthreads();

    if (t < NPH) {
        float2 v[MODES];
        #pragma unroll
        for (int m = 0; m < MODES; m++)
            v[m] = make_float2((m == t) ? 1.0f : 0.0f, 0.0f);

        int nbefore = 0;
        #pragma unroll
        for (int d = 0; d < 8; d++) {
            const int nb  = (d & 1) ? 7 : 8;
            const int off = (d & 1);
            #pragma unroll
            for (int k = 0; k < 8; k++) {
                if (k < nb) {
                    float4 tg = trig[nbefore + k];
                    const int r0 = off + 2 * k;
                    float2 t0 = v[r0], t1 = v[r0 + 1];
                    float2 epct = make_float2(tg.z * tg.x, tg.w * tg.x);
                    float2 epst = make_float2(tg.z * tg.y, tg.w * tg.y);
                    float2 n0 = cmul(epct, t0);
                    n0.x -= tg.y * t1.x;  n0.y -= tg.y * t1.y;
                    float2 n1 = cmul(epst, t0);
                    n1.x += tg.x * t1.x;  n1.y += tg.x * t1.y;
                    v[r0] = n0;  v[r0 + 1] = n1;
                }
            }
            nbefore += nb;
        }
        #pragma unroll
        for (int m = 0; m < MODES; m++)
            g_V[n * (NPH * MODES) + t * MODES + m] = v[m];
    }
}

// ---------------------------------------------------------------------------
// Kernel B (triangular): one warp per pair (a,b), bg >= qa macro-tiles only.
// G stored column-major packed (ull) -> column loads are LDS.128 broadcasts.
// Row-sum updates via fma.rn.f32x2 on native 64-bit regs (no packing movs).
// ---------------------------------------------------------------------------
#define VROW 18   // padded row stride (float2 units)

__global__ void __launch_bounds__(256) pair_kernel_tri(float* __restrict__ Kout)
{
    const int tid  = threadIdx.x;
    const int w    = tid >> 5;
    const int lane = tid & 31;

    // Decode macro-tile: t in [0,528) -> (bg, qa) with qa <= bg
    const int tIdx = blockIdx.x >> 3;
    const int ai   = blockIdx.x & 7;
    int bg = (int)((sqrtf(8.0f * (float)tIdx + 1.0f) - 1.0f) * 0.5f);
    if ((bg + 1) * (bg + 2) / 2 <= tIdx) bg++;
    if (bg * (bg + 1) / 2 > tIdx) bg--;
    const int qa   = tIdx - bg * (bg + 1) / 2;
    const int a    = qa * 8 + ai;
    const int bcol = bg * 8 + w;

    __shared__ alignas(16) float2 sVa[NPH * VROW];      // [i*18 + m]
    __shared__ alignas(16) float2 sVb[8][NPH * VROW];   // [w][j*18 + m]
    __shared__ alignas(16) ull    sAT[8][64];           // column-major: [w][j*8 + i]

    if (tid < NPH * MODES) {
        const int row = tid >> 4, m = tid & 15;
        sVa[row * VROW + m] = g_V[a * (NPH * MODES) + tid];
    }
    #pragma unroll
    for (int r = 0; r < 4; r++) {
        const int idx = lane + r * 32;
        const int row = idx >> 4, m = idx & 15;
        sVb[w][row * VROW + m] = g_V[bcol * (NPH * MODES) + idx];
    }
    __syncthreads();

    if (bcol < a) return;
    if (bcol == a) {
        if (lane == 0) Kout[a * NSAMP + a] = 1.0f;
        return;
    }

    // G[i][j] = sum_m conj(Va[m][i]) * Vb[m][j]; lane computes 2 entries.
    #pragma unroll
    for (int e = 0; e < 2; e++) {
        const int idx = lane + e * 32;
        const int i = idx >> 3, j = idx & 7;
        const float4* pa = (const float4*)&sVa[i * VROW];
        const float4* pb = (const float4*)&sVb[w][j * VROW];
        float2 acc = make_float2(0.0f, 0.0f);
        #pragma unroll
        for (int mm = 0; mm < 8; mm++) {
            float4 va2 = pa[mm];
            float4 vb2 = pb[mm];
            acc.x += va2.x * vb2.x + va2.y * vb2.y;
            acc.y += va2.x * vb2.y - va2.y * vb2.x;
            acc.x += va2.z * vb2.z + va2.w * vb2.w;
            acc.y += va2.z * vb2.w - va2.w * vb2.z;
        }
        sAT[w][j * 8 + i] = pack2(acc.x, acc.y);   // column-major store
    }
    __syncwarp();

    // Register-cache columns 0..1 (flip 6 of 7 inner Gray steps); LDS.128 loads.
    ull cr0[8], cr1[8];
    {
        const ulonglong2* c0 = (const ulonglong2*)&sAT[w][0];
        const ulonglong2* c1 = (const ulonglong2*)&sAT[w][8];
        #pragma unroll
        for (int q = 0; q < 4; q++) {
            ulonglong2 v0 = c0[q], v1 = c1[q];
            cr0[2*q] = v0.x; cr0[2*q+1] = v0.y;
            cr1[2*q] = v1.x; cr1[2*q+1] = v1.y;
        }
    }

    // Initial subset: gray(8*lane) = (lane<<3) ^ (lane<<2), bits >= 2 only.
    unsigned g = (((unsigned)lane << 3) ^ ((unsigned)lane << 2)) & 0xFFu;

    ull rs[8];
    #pragma unroll
    for (int i = 0; i < 8; i++) rs[i] = 0ull;

    #pragma unroll
    for (int jb = 2; jb < 8; jb++) {
        const float msk = (float)((g >> jb) & 1u);
        const ull mp = pack2(msk, msk);
        const ulonglong2* col = (const ulonglong2*)&sAT[w][jb * 8];
        #pragma unroll
        for (int q = 0; q < 4; q++) {
            ulonglong2 cv = col[q];
            rs[2*q]   = ffma2p(mp, cv.x, rs[2*q]);
            rs[2*q+1] = ffma2p(mp, cv.y, rs[2*q+1]);
        }
    }

    float2 acc = make_float2(0.0f, 0.0f);
    const int CTZ[8] = {0, 0, 1, 0, 2, 0, 1, 0};

    #pragma unroll
    for (int k = 0; k < 8; k++) {
        if (k > 0) {
            const int jb = CTZ[k];
            g ^= (1u << jb);
            const float s = ((g >> jb) & 1u) ? 1.0f : -1.0f;
            const ull sp = pack2(s, s);
            if (jb == 0) {
                #pragma unroll
                for (int i = 0; i < 8; i++) rs[i] = ffma2p(sp, cr0[i], rs[i]);
            } else if (jb == 1) {
                #pragma unroll
                for (int i = 0; i < 8; i++) rs[i] = ffma2p(sp, cr1[i], rs[i]);
            } else {
                const ulonglong2* col = (const ulonglong2*)&sAT[w][2 * 8];
                #pragma unroll
                for (int q = 0; q < 4; q++) {
                    ulonglong2 cv = col[q];
                    rs[2*q]   = ffma2p(sp, cv.x, rs[2*q]);
                    rs[2*q+1] = ffma2p(sp, cv.y, rs[2*q+1]);
                }
            }
        }
        // product of 8 complex row sums (tree for ILP); unpack = reg aliasing
        float2 r0 = unpack2(rs[0]), r1 = unpack2(rs[1]);
        float2 r2 = unpack2(rs[2]), r3 = unpack2(rs[3]);
        float2 r4 = unpack2(rs[4]), r5 = unpack2(rs[5]);
        float2 r6 = unpack2(rs[6]), r7 = unpack2(rs[7]);
        float2 p01 = cmul(r0, r1);
        float2 p23 = cmul(r2, r3);
        float2 p45 = cmul(r4, r5);
        float2 p67 = cmul(r6, r7);
        float2 p = cmul(cmul(p01, p23), cmul(p45, p67));
        if (k & 1) { acc.x -= p.x; acc.y -= p.y; }
        else       { acc.x += p.x; acc.y += p.y; }
    }

    // Warp reduce (complex)
    #pragma unroll
    for (int off = 16; off > 0; off >>= 1) {
        acc.x += __shfl_xor_sync(0xFFFFFFFFu, acc.x, off);
        acc.y += __shfl_xor_sync(0xFFFFFFFFu, acc.y, off);
    }

    if (lane == 0) {
        float kv = acc.x * acc.x + acc.y * acc.y;
        Kout[a * NSAMP + bcol] = kv;
        Kout[bcol * NSAMP + a] = kv;
    }
}

// ---------------------------------------------------------------------------
extern "C" void kernel_launch(void* const* d_in, const int* in_sizes, int n_in,
                              void* d_out, int out_size)
{
    const float* x = (const float*)d_in[0];   // (256, 64)
    const float* W = (const float*)d_in[1];   // (120, 64)
    const float* b = (const float*)d_in[2];   // (120,)
    float* out = (float*)d_out;               // [x_emb (30720) | K (65536)]

    emb_v_kernel<<<NSAMP, 128>>>(x, W, b, out);
    pair_kernel_tri<<<528 * 8, 256>>>(out + NSAMP * EMB);
}

// round 10
// speedup vs baseline: 1.1576x; 1.0624x over previous
#include <cuda_runtime.h>
#include <cstdint>

#define NSAMP 256
#define EMB   120
#define DIN   64
#define MODES 16
#define NPH   8

#define PIf 3.14159265358979323846f

typedef unsigned long long ull;

// Persistent scratch for V, stored TRANSPOSED: [n][c][m] (c=0..7, m=0..15)
__device__ float2 g_V[NSAMP * NPH * MODES];

__device__ __forceinline__ float2 cmul(float2 a, float2 b) {
    return make_float2(a.x * b.x - a.y * b.y, a.x * b.y + a.y * b.x);
}

// Packed dual-FMA on native 64-bit operands (FFMA2, one issue slot)
__device__ __forceinline__ ull ffma2p(ull a, ull b, ull c) {
    ull d;
    asm("fma.rn.f32x2 %0, %1, %2, %3;" : "=l"(d) : "l"(a), "l"(b), "l"(c));
    return d;
}
__device__ __forceinline__ ull pack2(float x, float y) {
    ull d; asm("mov.b64 %0, {%1, %2};" : "=l"(d) : "f"(x), "f"(y)); return d;
}
__device__ __forceinline__ float2 unpack2(ull a) {
    float2 f; asm("mov.b64 {%0, %1}, %2;" : "=f"(f.x), "=f"(f.y) : "l"(a)); return f;
}

// ---------------------------------------------------------------------------
// Kernel A: x_emb = sigmoid(x @ W^T + b); build V[n] (16x8 complex) per sample
// ---------------------------------------------------------------------------
__global__ void __launch_bounds__(128) emb_v_kernel(
    const float* __restrict__ x,
    const float* __restrict__ W,
    const float* __restrict__ b,
    float* __restrict__ out_emb)
{
    const int n = blockIdx.x;
    const int t = threadIdx.x;

    __shared__ float xs[DIN];
    __shared__ float semb[EMB];
    __shared__ float4 trig[60];

    if (t < DIN) xs[t] = x[n * DIN + t];
    __syncthreads();

    if (t < EMB) {
        float acc = b[t];
        const float* wr = W + t * DIN;
        #pragma unroll
        for (int j = 0; j < DIN; j++) acc += xs[j] * wr[j];
        float s = 1.0f / (1.0f + expf(-acc));
        semb[t] = s;
        out_emb[n * EMB + t] = s;
    }
    __syncthreads();

    if (t < 60) {
        float th = semb[2 * t]     * (0.5f * PIf);
        float ph = semb[2 * t + 1] * (2.0f * PIf);
        float st_, ct_, sp_, cp_;
        sincosf(th, &st_, &ct_);
        sincosf(ph, &sp_, &cp_);
        trig[t] = make_float4(ct_, st_, cp_, sp_);
    }
    __syncthreads();

    if (t < NPH) {
        float2 v[MODES];
        #pragma unroll
        for (int m = 0; m < MODES; m++)
            v[m] = make_float2((m == t) ? 1.0f : 0.0f, 0.0f);

        int nbefore = 0;
        #pragma unroll
        for (int d = 0; d < 8; d++) {
            const int nb  = (d & 1) ? 7 : 8;
            const int off = (d & 1);
            #pragma unroll
            for (int k = 0; k < 8; k++) {
                if (k < nb) {
                    float4 tg = trig[nbefore + k];
                    const int r0 = off + 2 * k;
                    float2 t0 = v[r0], t1 = v[r0 + 1];
                    float2 epct = make_float2(tg.z * tg.x, tg.w * tg.x);
                    float2 epst = make_float2(tg.z * tg.y, tg.w * tg.y);
                    float2 n0 = cmul(epct, t0);
                    n0.x -= tg.y * t1.x;  n0.y -= tg.y * t1.y;
                    float2 n1 = cmul(epst, t0);
                    n1.x += tg.x * t1.x;  n1.y += tg.x * t1.y;
                    v[r0] = n0;  v[r0 + 1] = n1;
                }
            }
            nbefore += nb;
        }
        #pragma unroll
        for (int m = 0; m < MODES; m++)
            g_V[n * (NPH * MODES) + t * MODES + m] = v[m];
    }
}

// ---------------------------------------------------------------------------
// Kernel B (triangular, GLYNN): one warp per pair (a,b), bg >= qa tiles.
// perm(G) = 2^{1-8} * sum over 128 delta-assignments (Gray coded) of
//   sign * prod_j S_j,  S_j = sum_i delta_i G[i][j].
// Lane t handles Gray indices 4t..4t+3: inner flips touch only rows 1,2.
// ---------------------------------------------------------------------------
#define VROW 18   // padded row stride (float2 units)

__global__ void __launch_bounds__(256) pair_kernel_tri(float* __restrict__ Kout)
{
    const int tid  = threadIdx.x;
    const int w    = tid >> 5;
    const int lane = tid & 31;

    // Decode macro-tile: t in [0,528) -> (bg, qa) with qa <= bg
    const int tIdx = blockIdx.x >> 3;
    const int ai   = blockIdx.x & 7;
    int bg = (int)((sqrtf(8.0f * (float)tIdx + 1.0f) - 1.0f) * 0.5f);
    if ((bg + 1) * (bg + 2) / 2 <= tIdx) bg++;
    if (bg * (bg + 1) / 2 > tIdx) bg--;
    const int qa   = tIdx - bg * (bg + 1) / 2;
    const int a    = qa * 8 + ai;
    const int bcol = bg * 8 + w;

    __shared__ alignas(16) float2 sVa[NPH * VROW];      // [i*18 + m]
    __shared__ alignas(16) float2 sVb[8][NPH * VROW];   // [w][j*18 + m]
    __shared__ alignas(16) ull    sAR[8][64];           // row-major: [w][i*8 + j]
    __shared__ alignas(16) ull    sRall[8][8];          // column sums over all rows

    if (tid < NPH * MODES) {
        const int row = tid >> 4, m = tid & 15;
        sVa[row * VROW + m] = g_V[a * (NPH * MODES) + tid];
    }
    #pragma unroll
    for (int r = 0; r < 4; r++) {
        const int idx = lane + r * 32;
        const int row = idx >> 4, m = idx & 15;
        sVb[w][row * VROW + m] = g_V[bcol * (NPH * MODES) + idx];
    }
    __syncthreads();

    if (bcol < a) return;
    if (bcol == a) {
        if (lane == 0) Kout[a * NSAMP + a] = 1.0f;
        return;
    }

    // G[i][j] = sum_m conj(Va[m][i]) * Vb[m][j]; lane computes 2 entries.
    #pragma unroll
    for (int e = 0; e < 2; e++) {
        const int idx = lane + e * 32;
        const int i = idx >> 3, j = idx & 7;
        const float4* pa = (const float4*)&sVa[i * VROW];
        const float4* pb = (const float4*)&sVb[w][j * VROW];
        float2 acc = make_float2(0.0f, 0.0f);
        #pragma unroll
        for (int mm = 0; mm < 8; mm++) {
            float4 va2 = pa[mm];
            float4 vb2 = pb[mm];
            acc.x += va2.x * vb2.x + va2.y * vb2.y;
            acc.y += va2.x * vb2.y - va2.y * vb2.x;
            acc.x += va2.z * vb2.z + va2.w * vb2.w;
            acc.y += va2.z * vb2.w - va2.w * vb2.z;
        }
        sAR[w][idx] = pack2(acc.x, acc.y);   // row-major store: [i*8 + j]
    }
    __syncwarp();

    // Column sums over all rows: R_all[j] = sum_i G[i][j]  (lanes 0..7)
    if (lane < 8) {
        float2 s = make_float2(0.0f, 0.0f);
        #pragma unroll
        for (int i = 0; i < 8; i++) {
            float2 v = unpack2(sAR[w][i * 8 + lane]);
            s.x += v.x; s.y += v.y;
        }
        sRall[w][lane] = pack2(s.x, s.y);
    }
    __syncwarp();

    // Register-cache row 1 (bit 0: flips at k=1 and k=3).
    ull rr1[8];
    {
        const ulonglong2* r1 = (const ulonglong2*)&sAR[w][8];
        #pragma unroll
        for (int q = 0; q < 4; q++) {
            ulonglong2 v = r1[q];
            rr1[2*q] = v.x; rr1[2*q+1] = v.y;
        }
    }

    // Gray state for this lane: g = gray(4*lane) over 7 bits (bit b <-> row b+1).
    // bit 0 of gray(4t) is always 0.
    unsigned g = ((4u * lane) ^ (2u * lane)) & 0x7Fu;

    // Init S = R_all - 2 * sum_{set bits b=1..6} row_{b+1}
    ull S[8];
    {
        const ulonglong2* ra = (const ulonglong2*)&sRall[w][0];
        #pragma unroll
        for (int q = 0; q < 4; q++) {
            ulonglong2 v = ra[q];
            S[2*q] = v.x; S[2*q+1] = v.y;
        }
    }
    #pragma unroll
    for (int b = 1; b < 7; b++) {
        const float msk = -2.0f * (float)((g >> b) & 1u);
        const ull mp = pack2(msk, msk);
        const ulonglong2* row = (const ulonglong2*)&sAR[w][(b + 1) * 8];
        #pragma unroll
        for (int q = 0; q < 4; q++) {
            ulonglong2 rv = row[q];
            S[2*q]   = ffma2p(mp, rv.x, S[2*q]);
            S[2*q+1] = ffma2p(mp, rv.y, S[2*q+1]);
        }
    }

    float2 acc = make_float2(0.0f, 0.0f);

    #pragma unroll
    for (int k = 0; k < 4; k++) {
        // product of 8 complex column sums
        float2 s0 = unpack2(S[0]), s1 = unpack2(S[1]);
        float2 s2 = unpack2(S[2]), s3 = unpack2(S[3]);
        float2 s4 = unpack2(S[4]), s5 = unpack2(S[5]);
        float2 s6 = unpack2(S[6]), s7 = unpack2(S[7]);
        float2 p01 = cmul(s0, s1);
        float2 p23 = cmul(s2, s3);
        float2 p45 = cmul(s4, s5);
        float2 p67 = cmul(s6, s7);
        float2 p = cmul(cmul(p01, p23), cmul(p45, p67));
        // sign = (-1)^popcount(gray(4t+k)) = (-1)^(k&1)  (4t even)
        if (k & 1) { acc.x -= p.x; acc.y -= p.y; }
        else       { acc.x += p.x; acc.y += p.y; }

        if (k < 3) {
            const int b = (k == 1) ? 1 : 0;       // flip bit: k=0->0, k=1->1, k=2->0
            g ^= (1u << b);
            const float s = ((g >> b) & 1u) ? -2.0f : 2.0f;
            const ull sp = pack2(s, s);
            if (b == 0) {
                #pragma unroll
                for (int i = 0; i < 8; i++) S[i] = ffma2p(sp, rr1[i], S[i]);
            } else {
                const ulonglong2* row = (const ulonglong2*)&sAR[w][2 * 8];
                #pragma unroll
                for (int q = 0; q < 4; q++) {
                    ulonglong2 rv = row[q];
                    S[2*q]   = ffma2p(sp, rv.x, S[2*q]);
                    S[2*q+1] = ffma2p(sp, rv.y, S[2*q+1]);
                }
            }
        }
    }

    // Warp reduce (complex)
    #pragma unroll
    for (int off = 16; off > 0; off >>= 1) {
        acc.x += __shfl_xor_sync(0xFFFFFFFFu, acc.x, off);
        acc.y += __shfl_xor_sync(0xFFFFFFFFu, acc.y, off);
    }

    if (lane == 0) {
        // perm = acc / 128 ; K = |perm|^2 = |acc|^2 / 16384
        float kv = (acc.x * acc.x + acc.y * acc.y) * (1.0f / 16384.0f);
        Kout[a * NSAMP + bcol] = kv;
        Kout[bcol * NSAMP + a] = kv;
    }
}

// ---------------------------------------------------------------------------
extern "C" void kernel_launch(void* const* d_in, const int* in_sizes, int n_in,
                              void* d_out, int out_size)
{
    const float* x = (const float*)d_in[0];   // (256, 64)
    const float* W = (const float*)d_in[1];   // (120, 64)
    const float* b = (const float*)d_in[2];   // (120,)
    float* out = (float*)d_out;               // [x_emb (30720) | K (65536)]

    emb_v_kernel<<<NSAMP, 128>>>(x, W, b, out);
    pair_kernel_tri<<<528 * 8, 256>>>(out + NSAMP * EMB);
}